// round 5
// baseline (speedup 1.0000x reference)
#include <cuda_runtime.h>
#include <cuda_fp16.h>

typedef unsigned long long ull;

// Problem constants
#define BB   512
#define TT   1024
#define TM1  1023
#define II   32
#define EE   32
#define HH   256
#define G3   768
#define KIN  64

// Cluster config: 64 clusters x 2 CTAs. Each cluster owns 8 batch elements;
// each CTA owns 384 gate rows (hidden-unit slice {u, u+256, u+512}).
#define CLSZ 2
#define BPC  8                 // batches per cluster
#define NB   (BB / BPC * CLSZ) // 128 CTAs
#define NT   384

// ---- transposed fp16 weights, 16B-grouped along k (same layout as R4) ----
__device__ __align__(16) __half2 W4I0[KIN/8][G3][4];
__device__ __align__(16) __half2 W4H0[HH /8][G3][4];
__device__ __align__(16) __half2 W4I1[HH /8][G3][4];
__device__ __align__(16) __half2 W4H1[HH /8][G3][4];
__device__ float WOUTT[HH][II];

__global__ void prep_kernel(const float* __restrict__ wih0, const float* __restrict__ whh0,
                            const float* __restrict__ wih1, const float* __restrict__ whh1,
                            const float* __restrict__ wout)
{
    const int S0 = (KIN/8) * G3;
    const int S1 = (HH /8) * G3;
    int idx = blockIdx.x * blockDim.x + threadIdx.x;
    if (idx < S0) {
        int k8 = idx / G3, g = idx % G3;
        const float* b = wih0 + g * KIN + 8 * k8;
#pragma unroll
        for (int j = 0; j < 4; ++j) W4I0[k8][g][j] = __floats2half2_rn(b[2*j], b[2*j+1]);
    } else if (idx < S0 + S1) {
        int r = idx - S0; int k8 = r / G3, g = r % G3;
        const float* b = whh0 + g * HH + 8 * k8;
#pragma unroll
        for (int j = 0; j < 4; ++j) W4H0[k8][g][j] = __floats2half2_rn(b[2*j], b[2*j+1]);
    } else if (idx < S0 + 2*S1) {
        int r = idx - S0 - S1; int k8 = r / G3, g = r % G3;
        const float* b = wih1 + g * HH + 8 * k8;
#pragma unroll
        for (int j = 0; j < 4; ++j) W4I1[k8][g][j] = __floats2half2_rn(b[2*j], b[2*j+1]);
    } else if (idx < S0 + 3*S1) {
        int r = idx - S0 - 2*S1; int k8 = r / G3, g = r % G3;
        const float* b = whh1 + g * HH + 8 * k8;
#pragma unroll
        for (int j = 0; j < 4; ++j) W4H1[k8][g][j] = __floats2half2_rn(b[2*j], b[2*j+1]);
    } else if (idx < S0 + 3*S1 + HH*II) {
        int r = idx - S0 - 3*S1; int k = r / II, i = r % II;
        WOUTT[k][i] = wout[i*HH + k];
    }
}

// ---- packed f32x2 helpers ----
__device__ __forceinline__ ull pack2(float a, float b) {
    ull r; asm("mov.b64 %0, {%1, %2};" : "=l"(r) : "f"(a), "f"(b)); return r;
}
__device__ __forceinline__ void unpack2(ull v, float& a, float& b) {
    asm("mov.b64 {%0, %1}, %2;" : "=f"(a), "=f"(b) : "l"(v));
}
__device__ __forceinline__ ull fma2(ull a, ull b, ull c) {
    ull d; asm("fma.rn.f32x2 %0, %1, %2, %3;" : "=l"(d) : "l"(a), "l"(b), "l"(c)); return d;
}
__device__ __forceinline__ float sigf(float x) {
    return __fdividef(1.0f, 1.0f + __expf(-x));
}
__device__ __forceinline__ float tanhfast(float x) {
    return 2.0f * sigf(2.0f * x) - 1.0f;
}

// ---- cluster helpers ----
__device__ __forceinline__ unsigned cluster_rank() {
    unsigned r; asm("mov.u32 %0, %%cluster_ctarank;" : "=r"(r)); return r;
}
__device__ __forceinline__ unsigned smem_u32(const void* p) {
    return (unsigned)__cvta_generic_to_shared(p);
}
__device__ __forceinline__ unsigned mapa_rank(unsigned addr, unsigned rank) {
    unsigned d; asm("mapa.shared::cluster.u32 %0, %1, %2;" : "=r"(d) : "r"(addr), "r"(rank));
    return d;
}
__device__ __forceinline__ void st_cluster_f4(unsigned addr, float4 v) {
    asm volatile("st.shared::cluster.v4.f32 [%0], {%1, %2, %3, %4};"
                 :: "r"(addr), "f"(v.x), "f"(v.y), "f"(v.z), "f"(v.w) : "memory");
}
#define CLUSTER_SYNC() do { \
    asm volatile("barrier.cluster.arrive.aligned;" ::: "memory"); \
    asm volatile("barrier.cluster.wait.aligned;"   ::: "memory"); \
} while (0)

// single-row, 8-batch packed GEMV accumulate (4 f32x2 chains)
template<int NK8>
__device__ __forceinline__ void gemv8(const __half2 (*__restrict__ W)[G3][4],
                                      int grow, const float (*__restrict__ act)[8],
                                      ull acc[4])
{
#pragma unroll 4
    for (int kb = 0; kb < NK8; ++kb) {
        const uint4 w = *reinterpret_cast<const uint4*>(&W[kb][grow][0]);
#pragma unroll
        for (int j = 0; j < 4; ++j) {
            const float2 f = __half22float2(reinterpret_cast<const __half2*>(&w)[j]);
            const int k = kb * 8 + 2 * j;
            const ulonglong2 xe0 = *reinterpret_cast<const ulonglong2*>(&act[k    ][0]);
            const ulonglong2 xe1 = *reinterpret_cast<const ulonglong2*>(&act[k    ][4]);
            const ulonglong2 xo0 = *reinterpret_cast<const ulonglong2*>(&act[k + 1][0]);
            const ulonglong2 xo1 = *reinterpret_cast<const ulonglong2*>(&act[k + 1][4]);
            const ull we = pack2(f.x, f.x);
            const ull wo = pack2(f.y, f.y);
            acc[0] = fma2(we, xe0.x, acc[0]);
            acc[1] = fma2(we, xe0.y, acc[1]);
            acc[2] = fma2(we, xe1.x, acc[2]);
            acc[3] = fma2(we, xe1.y, acc[3]);
            acc[0] = fma2(wo, xo0.x, acc[0]);
            acc[1] = fma2(wo, xo0.y, acc[1]);
            acc[2] = fma2(wo, xo1.x, acc[2]);
            acc[3] = fma2(wo, xo1.y, acc[3]);
        }
    }
}

__device__ __forceinline__ void gate4(const float4 gir, const float4 ghr,
                                      const float4 giz, const float4 ghz,
                                      const float4 gin, const float4 ghn,
                                      float4& h)
{
    const float r0 = sigf(gir.x + ghr.x), r1 = sigf(gir.y + ghr.y);
    const float r2 = sigf(gir.z + ghr.z), r3 = sigf(gir.w + ghr.w);
    const float z0 = sigf(giz.x + ghz.x), z1 = sigf(giz.y + ghz.y);
    const float z2 = sigf(giz.z + ghz.z), z3 = sigf(giz.w + ghz.w);
    const float n0 = tanhfast(gin.x + r0 * ghn.x);
    const float n1 = tanhfast(gin.y + r1 * ghn.y);
    const float n2 = tanhfast(gin.z + r2 * ghn.z);
    const float n3 = tanhfast(gin.w + r3 * ghn.w);
    h.x = (1.0f - z0) * n0 + z0 * h.x;
    h.y = (1.0f - z1) * n1 + z1 * h.y;
    h.z = (1.0f - z2) * n2 + z2 * h.z;
    h.w = (1.0f - z3) * n3 + z3 * h.w;
}

__global__ void __launch_bounds__(NT, 1) __cluster_dims__(CLSZ, 1, 1)
arrnn_kernel(const float* __restrict__ X,
             const float* __restrict__ ENC,
             const int*   __restrict__ MASK,
             const float* __restrict__ bih0, const float* __restrict__ bhh0,
             const float* __restrict__ bih1, const float* __restrict__ bhh1,
             const float* __restrict__ bout,
             float* __restrict__ outseq, float* __restrict__ outh1,
             int write_h1)
{
    __shared__ __align__(16) float inp8[KIN][8];   //  2 KB
    __shared__ __align__(16) float h0f[HH][8];     //  8 KB (full hidden, both slices)
    __shared__ __align__(16) float h1f[HH][8];     //  8 KB
    __shared__ __align__(16) float gi8[NT][8];     // 12 KB (local rows)
    __shared__ __align__(16) float gh8[NT][8];     // 12 KB
    __shared__ __align__(16) float yp8[II][8];     //  1 KB

    const int tid  = threadIdx.x;
    const unsigned rank = cluster_rank();
    const unsigned peer = rank ^ 1u;
    const int b0 = (blockIdx.x >> 1) * BPC;        // cluster's batch base

    // local row -> global gate row: q = tid/128, lu = tid%128
    const int q  = tid >> 7;
    const int lu = tid & 127;
    const int grow = q * 256 + (int)rank * 128 + lu;

    // zero-init shared state (both CTAs zero their full arrays)
    for (int i = tid; i < HH * 8; i += NT) { (&h0f[0][0])[i] = 0.0f; (&h1f[0][0])[i] = 0.0f; }
    for (int i = tid; i < II * 8; i += NT) (&yp8[0][0])[i] = 0.0f;
    __syncthreads();
    CLUSTER_SYNC();   // both CTAs initialized before any DSMEM traffic

    const ull bi0 = pack2(bih0[grow], bih0[grow]);
    const ull bh0 = pack2(bhh0[grow], bhh0[grow]);
    const ull bi1 = pack2(bih1[grow], bih1[grow]);
    const ull bh1 = pack2(bhh1[grow], bhh1[grow]);

    for (int t = 0; t < TM1; ++t) {
        // ---- Phase A: build packed input [x_or_y | enc(t+1)] for all 8 batches ----
        for (int i = tid; i < KIN * 8; i += NT) {
            const int k = i >> 3;
            const int b = i & 7;
            const int gb = b0 + b;
            float v;
            if (k < II) {
                const bool keep = (t == 0) || (MASK[gb * TT + t] != 0);
                v = keep ? X[((size_t)gb * TT + t) * II + k] : yp8[k][b];
            } else {
                v = ENC[((size_t)gb * TT + (t + 1)) * EE + (k - II)];
            }
            inp8[k][b] = v;
        }
        __syncthreads();

        // ---- Phase B: layer-0 gate pre-activations (own 384 rows x 8 batches) ----
        {
            ull ai[4] = {bi0, bi0, bi0, bi0};
            gemv8<KIN/8>(W4I0, grow, inp8, ai);
            ull ah[4] = {bh0, bh0, bh0, bh0};
            gemv8<HH/8>(W4H0, grow, h0f, ah);
            ulonglong2 v;
            v.x = ai[0]; v.y = ai[1]; *reinterpret_cast<ulonglong2*>(&gi8[tid][0]) = v;
            v.x = ai[2]; v.y = ai[3]; *reinterpret_cast<ulonglong2*>(&gi8[tid][4]) = v;
            v.x = ah[0]; v.y = ah[1]; *reinterpret_cast<ulonglong2*>(&gh8[tid][0]) = v;
            v.x = ah[2]; v.y = ah[3]; *reinterpret_cast<ulonglong2*>(&gh8[tid][4]) = v;
        }
        CLUSTER_SYNC();  // peer done READING old h0f before we overwrite it

        // ---- Phase C: update own h0 slice, push to peer ----
        if (tid < 2 * 128) {
            const int u  = (int)rank * 128 + (tid >> 1);
            const int p  = tid & 1;                 // batch half (4 floats)
            const int lr = tid >> 1;
            float4 h = *reinterpret_cast<const float4*>(&h0f[u][4*p]);
            gate4(*reinterpret_cast<const float4*>(&gi8[lr      ][4*p]),
                  *reinterpret_cast<const float4*>(&gh8[lr      ][4*p]),
                  *reinterpret_cast<const float4*>(&gi8[lr + 128][4*p]),
                  *reinterpret_cast<const float4*>(&gh8[lr + 128][4*p]),
                  *reinterpret_cast<const float4*>(&gi8[lr + 256][4*p]),
                  *reinterpret_cast<const float4*>(&gh8[lr + 256][4*p]), h);
            *reinterpret_cast<float4*>(&h0f[u][4*p]) = h;
            st_cluster_f4(mapa_rank(smem_u32(&h0f[u][4*p]), peer), h);
        }
        CLUSTER_SYNC();  // full new h0 visible in both CTAs

        // ---- Phase D: layer-1 gate pre-activations ----
        {
            ull ai[4] = {bi1, bi1, bi1, bi1};
            gemv8<HH/8>(W4I1, grow, h0f, ai);
            ull ah[4] = {bh1, bh1, bh1, bh1};
            gemv8<HH/8>(W4H1, grow, h1f, ah);
            ulonglong2 v;
            v.x = ai[0]; v.y = ai[1]; *reinterpret_cast<ulonglong2*>(&gi8[tid][0]) = v;
            v.x = ai[2]; v.y = ai[3]; *reinterpret_cast<ulonglong2*>(&gi8[tid][4]) = v;
            v.x = ah[0]; v.y = ah[1]; *reinterpret_cast<ulonglong2*>(&gh8[tid][0]) = v;
            v.x = ah[2]; v.y = ah[3]; *reinterpret_cast<ulonglong2*>(&gh8[tid][4]) = v;
        }
        CLUSTER_SYNC();  // peer done READING old h1f

        // ---- Phase E: update own h1 slice, push to peer ----
        if (tid < 2 * 128) {
            const int u  = (int)rank * 128 + (tid >> 1);
            const int p  = tid & 1;
            const int lr = tid >> 1;
            float4 h = *reinterpret_cast<const float4*>(&h1f[u][4*p]);
            gate4(*reinterpret_cast<const float4*>(&gi8[lr      ][4*p]),
                  *reinterpret_cast<const float4*>(&gh8[lr      ][4*p]),
                  *reinterpret_cast<const float4*>(&gi8[lr + 128][4*p]),
                  *reinterpret_cast<const float4*>(&gh8[lr + 128][4*p]),
                  *reinterpret_cast<const float4*>(&gi8[lr + 256][4*p]),
                  *reinterpret_cast<const float4*>(&gh8[lr + 256][4*p]), h);
            *reinterpret_cast<float4*>(&h1f[u][4*p]) = h;
            st_cluster_f4(mapa_rank(smem_u32(&h1f[u][4*p]), peer), h);
        }
        CLUSTER_SYNC();  // full new h1 visible in both CTAs

        // ---- Phase F: readout (both CTAs compute all 8 batches; store own half) ----
        if (tid < 4 * II) {
            const int p = tid >> 5;                 // batch pair 0..3
            const int i = tid & 31;
            const float bo = __ldg(&bout[i]);
            ull a0 = pack2(bo, bo);
            ull a1 = pack2(0.0f, 0.0f);
            ull a2 = a1, a3 = a1;
#pragma unroll 8
            for (int k = 0; k < HH; k += 4) {
                const float w0 = WOUTT[k    ][i];
                const float w1 = WOUTT[k + 1][i];
                const float w2 = WOUTT[k + 2][i];
                const float w3 = WOUTT[k + 3][i];
                a0 = fma2(pack2(w0, w0), *reinterpret_cast<const ull*>(&h1f[k    ][2*p]), a0);
                a1 = fma2(pack2(w1, w1), *reinterpret_cast<const ull*>(&h1f[k + 1][2*p]), a1);
                a2 = fma2(pack2(w2, w2), *reinterpret_cast<const ull*>(&h1f[k + 2][2*p]), a2);
                a3 = fma2(pack2(w3, w3), *reinterpret_cast<const ull*>(&h1f[k + 3][2*p]), a3);
            }
            float s0x, s0y, s1x, s1y, s2x, s2y, s3x, s3y;
            unpack2(a0, s0x, s0y); unpack2(a1, s1x, s1y);
            unpack2(a2, s2x, s2y); unpack2(a3, s3x, s3y);
            const float y0 = (s0x + s1x) + (s2x + s3x);
            const float y1 = (s0y + s1y) + (s2y + s3y);
            yp8[i][2*p]     = y0;
            yp8[i][2*p + 1] = y1;
            if ((unsigned)(p >> 1) == rank) {       // split the global stores
                outseq[((size_t)(b0 + 2*p    ) * TM1 + t) * II + i] = y0;
                outseq[((size_t)(b0 + 2*p + 1) * TM1 + t) * II + i] = y1;
            }
        }
        __syncthreads();
    }

    // final hidden state: rank r writes batches [4r, 4r+4)
    if (write_h1) {
        for (int i = tid; i < 4 * HH; i += NT) {
            const int bl = i >> 8;                  // 0..3
            const int j  = i & (HH - 1);
            const int b  = b0 + (int)rank * 4 + bl;
            outh1[(size_t)b * HH + j] = h1f[j][(int)rank * 4 + bl];
        }
    }
}

extern "C" void kernel_launch(void* const* d_in, const int* in_sizes, int n_in,
                              void* d_out, int out_size) {
    const float* X    = (const float*)d_in[0];
    const float* ENC  = (const float*)d_in[1];
    const int*   MASK = (const int*)d_in[2];
    const float* wih0 = (const float*)d_in[3];
    const float* whh0 = (const float*)d_in[4];
    const float* bih0 = (const float*)d_in[5];
    const float* bhh0 = (const float*)d_in[6];
    const float* wih1 = (const float*)d_in[7];
    const float* whh1 = (const float*)d_in[8];
    const float* bih1 = (const float*)d_in[9];
    const float* bhh1 = (const float*)d_in[10];
    const float* wout = (const float*)d_in[11];
    const float* bout = (const float*)d_in[12];

    float* outseq = (float*)d_out;
    const int seqsz = BB * TM1 * II;
    float* outh1  = outseq + seqsz;
    const int write_h1 = (out_size >= seqsz + BB * HH) ? 1 : 0;

    const int total = (KIN/8)*G3 + 3*(HH/8)*G3 + HH*II;
    prep_kernel<<<(total + 255) / 256, 256>>>(wih0, whh0, wih1, whh1, wout);

    arrnn_kernel<<<NB, NT>>>(X, ENC, MASK,
                             bih0, bhh0, bih1, bhh1, bout,
                             outseq, outh1, write_h1);
}

// round 6
// speedup vs baseline: 1.0002x; 1.0002x over previous
#include <cuda_runtime.h>
#include <cuda_fp16.h>

typedef unsigned long long ull;

// Problem constants
#define BB   512
#define TT   1024
#define TM1  1023
#define II   32
#define EE   32
#define HH   256
#define G3   768
#define KIN  64

// Cluster config: 64 clusters x 2 CTAs. Each cluster owns 8 batch elements;
// each CTA owns 384 gate rows (hidden-unit slice {u, u+256, u+512}).
#define CLSZ 2
#define BPC  8                 // batches per cluster
#define NB   (BB / BPC * CLSZ) // 128 CTAs
#define NT   384

// ---- transposed fp16 weights, 16B-grouped along k (same layout as R4) ----
__device__ __align__(16) __half2 W4I0[KIN/8][G3][4];
__device__ __align__(16) __half2 W4H0[HH /8][G3][4];
__device__ __align__(16) __half2 W4I1[HH /8][G3][4];
__device__ __align__(16) __half2 W4H1[HH /8][G3][4];
__device__ float WOUTT[HH][II];

__global__ void prep_kernel(const float* __restrict__ wih0, const float* __restrict__ whh0,
                            const float* __restrict__ wih1, const float* __restrict__ whh1,
                            const float* __restrict__ wout)
{
    const int S0 = (KIN/8) * G3;
    const int S1 = (HH /8) * G3;
    int idx = blockIdx.x * blockDim.x + threadIdx.x;
    if (idx < S0) {
        int k8 = idx / G3, g = idx % G3;
        const float* b = wih0 + g * KIN + 8 * k8;
#pragma unroll
        for (int j = 0; j < 4; ++j) W4I0[k8][g][j] = __floats2half2_rn(b[2*j], b[2*j+1]);
    } else if (idx < S0 + S1) {
        int r = idx - S0; int k8 = r / G3, g = r % G3;
        const float* b = whh0 + g * HH + 8 * k8;
#pragma unroll
        for (int j = 0; j < 4; ++j) W4H0[k8][g][j] = __floats2half2_rn(b[2*j], b[2*j+1]);
    } else if (idx < S0 + 2*S1) {
        int r = idx - S0 - S1; int k8 = r / G3, g = r % G3;
        const float* b = wih1 + g * HH + 8 * k8;
#pragma unroll
        for (int j = 0; j < 4; ++j) W4I1[k8][g][j] = __floats2half2_rn(b[2*j], b[2*j+1]);
    } else if (idx < S0 + 3*S1) {
        int r = idx - S0 - 2*S1; int k8 = r / G3, g = r % G3;
        const float* b = whh1 + g * HH + 8 * k8;
#pragma unroll
        for (int j = 0; j < 4; ++j) W4H1[k8][g][j] = __floats2half2_rn(b[2*j], b[2*j+1]);
    } else if (idx < S0 + 3*S1 + HH*II) {
        int r = idx - S0 - 3*S1; int k = r / II, i = r % II;
        WOUTT[k][i] = wout[i*HH + k];
    }
}

// ---- packed f32x2 helpers ----
__device__ __forceinline__ ull pack2(float a, float b) {
    ull r; asm("mov.b64 %0, {%1, %2};" : "=l"(r) : "f"(a), "f"(b)); return r;
}
__device__ __forceinline__ void unpack2(ull v, float& a, float& b) {
    asm("mov.b64 {%0, %1}, %2;" : "=f"(a), "=f"(b) : "l"(v));
}
__device__ __forceinline__ ull fma2(ull a, ull b, ull c) {
    ull d; asm("fma.rn.f32x2 %0, %1, %2, %3;" : "=l"(d) : "l"(a), "l"(b), "l"(c)); return d;
}
__device__ __forceinline__ float sigf(float x) {
    return __fdividef(1.0f, 1.0f + __expf(-x));
}
__device__ __forceinline__ float tanhfast(float x) {
    return 2.0f * sigf(2.0f * x) - 1.0f;
}

// ---- cluster helpers ----
__device__ __forceinline__ unsigned cluster_rank() {
    unsigned r; asm("mov.u32 %0, %%cluster_ctarank;" : "=r"(r)); return r;
}
__device__ __forceinline__ unsigned smem_u32(const void* p) {
    return (unsigned)__cvta_generic_to_shared(p);
}
__device__ __forceinline__ unsigned mapa_rank(unsigned addr, unsigned rank) {
    unsigned d; asm("mapa.shared::cluster.u32 %0, %1, %2;" : "=r"(d) : "r"(addr), "r"(rank));
    return d;
}
__device__ __forceinline__ void st_cluster_f4(unsigned addr, float4 v) {
    asm volatile("st.shared::cluster.v4.f32 [%0], {%1, %2, %3, %4};"
                 :: "r"(addr), "f"(v.x), "f"(v.y), "f"(v.z), "f"(v.w) : "memory");
}
#define CLUSTER_SYNC() do { \
    asm volatile("barrier.cluster.arrive.aligned;" ::: "memory"); \
    asm volatile("barrier.cluster.wait.aligned;"   ::: "memory"); \
} while (0)

// single-row, 8-batch packed GEMV accumulate (4 f32x2 chains)
template<int NK8>
__device__ __forceinline__ void gemv8(const __half2 (*__restrict__ W)[G3][4],
                                      int grow, const float (*__restrict__ act)[8],
                                      ull acc[4])
{
#pragma unroll 4
    for (int kb = 0; kb < NK8; ++kb) {
        const uint4 w = *reinterpret_cast<const uint4*>(&W[kb][grow][0]);
#pragma unroll
        for (int j = 0; j < 4; ++j) {
            const float2 f = __half22float2(reinterpret_cast<const __half2*>(&w)[j]);
            const int k = kb * 8 + 2 * j;
            const ulonglong2 xe0 = *reinterpret_cast<const ulonglong2*>(&act[k    ][0]);
            const ulonglong2 xe1 = *reinterpret_cast<const ulonglong2*>(&act[k    ][4]);
            const ulonglong2 xo0 = *reinterpret_cast<const ulonglong2*>(&act[k + 1][0]);
            const ulonglong2 xo1 = *reinterpret_cast<const ulonglong2*>(&act[k + 1][4]);
            const ull we = pack2(f.x, f.x);
            const ull wo = pack2(f.y, f.y);
            acc[0] = fma2(we, xe0.x, acc[0]);
            acc[1] = fma2(we, xe0.y, acc[1]);
            acc[2] = fma2(we, xe1.x, acc[2]);
            acc[3] = fma2(we, xe1.y, acc[3]);
            acc[0] = fma2(wo, xo0.x, acc[0]);
            acc[1] = fma2(wo, xo0.y, acc[1]);
            acc[2] = fma2(wo, xo1.x, acc[2]);
            acc[3] = fma2(wo, xo1.y, acc[3]);
        }
    }
}

__device__ __forceinline__ void gate4(const float4 gir, const float4 ghr,
                                      const float4 giz, const float4 ghz,
                                      const float4 gin, const float4 ghn,
                                      float4& h)
{
    const float r0 = sigf(gir.x + ghr.x), r1 = sigf(gir.y + ghr.y);
    const float r2 = sigf(gir.z + ghr.z), r3 = sigf(gir.w + ghr.w);
    const float z0 = sigf(giz.x + ghz.x), z1 = sigf(giz.y + ghz.y);
    const float z2 = sigf(giz.z + ghz.z), z3 = sigf(giz.w + ghz.w);
    const float n0 = tanhfast(gin.x + r0 * ghn.x);
    const float n1 = tanhfast(gin.y + r1 * ghn.y);
    const float n2 = tanhfast(gin.z + r2 * ghn.z);
    const float n3 = tanhfast(gin.w + r3 * ghn.w);
    h.x = (1.0f - z0) * n0 + z0 * h.x;
    h.y = (1.0f - z1) * n1 + z1 * h.y;
    h.z = (1.0f - z2) * n2 + z2 * h.z;
    h.w = (1.0f - z3) * n3 + z3 * h.w;
}

__global__ void __launch_bounds__(NT, 1) __cluster_dims__(CLSZ, 1, 1)
arrnn_kernel(const float* __restrict__ X,
             const float* __restrict__ ENC,
             const int*   __restrict__ MASK,
             const float* __restrict__ bih0, const float* __restrict__ bhh0,
             const float* __restrict__ bih1, const float* __restrict__ bhh1,
             const float* __restrict__ bout,
             float* __restrict__ outseq, float* __restrict__ outh1,
             int write_h1)
{
    __shared__ __align__(16) float inp8[KIN][8];   //  2 KB
    __shared__ __align__(16) float h0f[HH][8];     //  8 KB (full hidden, both slices)
    __shared__ __align__(16) float h1f[HH][8];     //  8 KB
    __shared__ __align__(16) float gi8[NT][8];     // 12 KB (local rows)
    __shared__ __align__(16) float gh8[NT][8];     // 12 KB
    __shared__ __align__(16) float yp8[II][8];     //  1 KB

    const int tid  = threadIdx.x;
    const unsigned rank = cluster_rank();
    const unsigned peer = rank ^ 1u;
    const int b0 = (blockIdx.x >> 1) * BPC;        // cluster's batch base

    // local row -> global gate row: q = tid/128, lu = tid%128
    const int q  = tid >> 7;
    const int lu = tid & 127;
    const int grow = q * 256 + (int)rank * 128 + lu;

    // zero-init shared state (both CTAs zero their full arrays)
    for (int i = tid; i < HH * 8; i += NT) { (&h0f[0][0])[i] = 0.0f; (&h1f[0][0])[i] = 0.0f; }
    for (int i = tid; i < II * 8; i += NT) (&yp8[0][0])[i] = 0.0f;
    __syncthreads();
    CLUSTER_SYNC();   // both CTAs initialized before any DSMEM traffic

    const ull bi0 = pack2(bih0[grow], bih0[grow]);
    const ull bh0 = pack2(bhh0[grow], bhh0[grow]);
    const ull bi1 = pack2(bih1[grow], bih1[grow]);
    const ull bh1 = pack2(bhh1[grow], bhh1[grow]);

    for (int t = 0; t < TM1; ++t) {
        // ---- Phase A: build packed input [x_or_y | enc(t+1)] for all 8 batches ----
        for (int i = tid; i < KIN * 8; i += NT) {
            const int k = i >> 3;
            const int b = i & 7;
            const int gb = b0 + b;
            float v;
            if (k < II) {
                const bool keep = (t == 0) || (MASK[gb * TT + t] != 0);
                v = keep ? X[((size_t)gb * TT + t) * II + k] : yp8[k][b];
            } else {
                v = ENC[((size_t)gb * TT + (t + 1)) * EE + (k - II)];
            }
            inp8[k][b] = v;
        }
        __syncthreads();

        // ---- Phase B: layer-0 gate pre-activations (own 384 rows x 8 batches) ----
        {
            ull ai[4] = {bi0, bi0, bi0, bi0};
            gemv8<KIN/8>(W4I0, grow, inp8, ai);
            ull ah[4] = {bh0, bh0, bh0, bh0};
            gemv8<HH/8>(W4H0, grow, h0f, ah);
            ulonglong2 v;
            v.x = ai[0]; v.y = ai[1]; *reinterpret_cast<ulonglong2*>(&gi8[tid][0]) = v;
            v.x = ai[2]; v.y = ai[3]; *reinterpret_cast<ulonglong2*>(&gi8[tid][4]) = v;
            v.x = ah[0]; v.y = ah[1]; *reinterpret_cast<ulonglong2*>(&gh8[tid][0]) = v;
            v.x = ah[2]; v.y = ah[3]; *reinterpret_cast<ulonglong2*>(&gh8[tid][4]) = v;
        }
        CLUSTER_SYNC();  // peer done READING old h0f before we overwrite it

        // ---- Phase C: update own h0 slice, push to peer ----
        if (tid < 2 * 128) {
            const int u  = (int)rank * 128 + (tid >> 1);
            const int p  = tid & 1;                 // batch half (4 floats)
            const int lr = tid >> 1;
            float4 h = *reinterpret_cast<const float4*>(&h0f[u][4*p]);
            gate4(*reinterpret_cast<const float4*>(&gi8[lr      ][4*p]),
                  *reinterpret_cast<const float4*>(&gh8[lr      ][4*p]),
                  *reinterpret_cast<const float4*>(&gi8[lr + 128][4*p]),
                  *reinterpret_cast<const float4*>(&gh8[lr + 128][4*p]),
                  *reinterpret_cast<const float4*>(&gi8[lr + 256][4*p]),
                  *reinterpret_cast<const float4*>(&gh8[lr + 256][4*p]), h);
            *reinterpret_cast<float4*>(&h0f[u][4*p]) = h;
            st_cluster_f4(mapa_rank(smem_u32(&h0f[u][4*p]), peer), h);
        }
        CLUSTER_SYNC();  // full new h0 visible in both CTAs

        // ---- Phase D: layer-1 gate pre-activations ----
        {
            ull ai[4] = {bi1, bi1, bi1, bi1};
            gemv8<HH/8>(W4I1, grow, h0f, ai);
            ull ah[4] = {bh1, bh1, bh1, bh1};
            gemv8<HH/8>(W4H1, grow, h1f, ah);
            ulonglong2 v;
            v.x = ai[0]; v.y = ai[1]; *reinterpret_cast<ulonglong2*>(&gi8[tid][0]) = v;
            v.x = ai[2]; v.y = ai[3]; *reinterpret_cast<ulonglong2*>(&gi8[tid][4]) = v;
            v.x = ah[0]; v.y = ah[1]; *reinterpret_cast<ulonglong2*>(&gh8[tid][0]) = v;
            v.x = ah[2]; v.y = ah[3]; *reinterpret_cast<ulonglong2*>(&gh8[tid][4]) = v;
        }
        CLUSTER_SYNC();  // peer done READING old h1f

        // ---- Phase E: update own h1 slice, push to peer ----
        if (tid < 2 * 128) {
            const int u  = (int)rank * 128 + (tid >> 1);
            const int p  = tid & 1;
            const int lr = tid >> 1;
            float4 h = *reinterpret_cast<const float4*>(&h1f[u][4*p]);
            gate4(*reinterpret_cast<const float4*>(&gi8[lr      ][4*p]),
                  *reinterpret_cast<const float4*>(&gh8[lr      ][4*p]),
                  *reinterpret_cast<const float4*>(&gi8[lr + 128][4*p]),
                  *reinterpret_cast<const float4*>(&gh8[lr + 128][4*p]),
                  *reinterpret_cast<const float4*>(&gi8[lr + 256][4*p]),
                  *reinterpret_cast<const float4*>(&gh8[lr + 256][4*p]), h);
            *reinterpret_cast<float4*>(&h1f[u][4*p]) = h;
            st_cluster_f4(mapa_rank(smem_u32(&h1f[u][4*p]), peer), h);
        }
        CLUSTER_SYNC();  // full new h1 visible in both CTAs

        // ---- Phase F: readout (both CTAs compute all 8 batches; store own half) ----
        if (tid < 4 * II) {
            const int p = tid >> 5;                 // batch pair 0..3
            const int i = tid & 31;
            const float bo = __ldg(&bout[i]);
            ull a0 = pack2(bo, bo);
            ull a1 = pack2(0.0f, 0.0f);
            ull a2 = a1, a3 = a1;
#pragma unroll 8
            for (int k = 0; k < HH; k += 4) {
                const float w0 = WOUTT[k    ][i];
                const float w1 = WOUTT[k + 1][i];
                const float w2 = WOUTT[k + 2][i];
                const float w3 = WOUTT[k + 3][i];
                a0 = fma2(pack2(w0, w0), *reinterpret_cast<const ull*>(&h1f[k    ][2*p]), a0);
                a1 = fma2(pack2(w1, w1), *reinterpret_cast<const ull*>(&h1f[k + 1][2*p]), a1);
                a2 = fma2(pack2(w2, w2), *reinterpret_cast<const ull*>(&h1f[k + 2][2*p]), a2);
                a3 = fma2(pack2(w3, w3), *reinterpret_cast<const ull*>(&h1f[k + 3][2*p]), a3);
            }
            float s0x, s0y, s1x, s1y, s2x, s2y, s3x, s3y;
            unpack2(a0, s0x, s0y); unpack2(a1, s1x, s1y);
            unpack2(a2, s2x, s2y); unpack2(a3, s3x, s3y);
            const float y0 = (s0x + s1x) + (s2x + s3x);
            const float y1 = (s0y + s1y) + (s2y + s3y);
            yp8[i][2*p]     = y0;
            yp8[i][2*p + 1] = y1;
            if ((unsigned)(p >> 1) == rank) {       // split the global stores
                outseq[((size_t)(b0 + 2*p    ) * TM1 + t) * II + i] = y0;
                outseq[((size_t)(b0 + 2*p + 1) * TM1 + t) * II + i] = y1;
            }
        }
        __syncthreads();
    }

    // final hidden state: rank r writes batches [4r, 4r+4)
    if (write_h1) {
        for (int i = tid; i < 4 * HH; i += NT) {
            const int bl = i >> 8;                  // 0..3
            const int j  = i & (HH - 1);
            const int b  = b0 + (int)rank * 4 + bl;
            outh1[(size_t)b * HH + j] = h1f[j][(int)rank * 4 + bl];
        }
    }
}

extern "C" void kernel_launch(void* const* d_in, const int* in_sizes, int n_in,
                              void* d_out, int out_size) {
    const float* X    = (const float*)d_in[0];
    const float* ENC  = (const float*)d_in[1];
    const int*   MASK = (const int*)d_in[2];
    const float* wih0 = (const float*)d_in[3];
    const float* whh0 = (const float*)d_in[4];
    const float* bih0 = (const float*)d_in[5];
    const float* bhh0 = (const float*)d_in[6];
    const float* wih1 = (const float*)d_in[7];
    const float* whh1 = (const float*)d_in[8];
    const float* bih1 = (const float*)d_in[9];
    const float* bhh1 = (const float*)d_in[10];
    const float* wout = (const float*)d_in[11];
    const float* bout = (const float*)d_in[12];

    float* outseq = (float*)d_out;
    const int seqsz = BB * TM1 * II;
    float* outh1  = outseq + seqsz;
    const int write_h1 = (out_size >= seqsz + BB * HH) ? 1 : 0;

    const int total = (KIN/8)*G3 + 3*(HH/8)*G3 + HH*II;
    prep_kernel<<<(total + 255) / 256, 256>>>(wih0, whh0, wih1, whh1, wout);

    arrnn_kernel<<<NB, NT>>>(X, ENC, MASK,
                             bih0, bhh0, bih1, bhh1, bout,
                             outseq, outh1, write_h1);
}

// round 8
// speedup vs baseline: 3.0962x; 3.0955x over previous
#include <cuda_runtime.h>
#include <cuda_fp16.h>
#include <cstdint>

typedef unsigned int u32;

#define BB   512
#define TT   1024
#define TM1  1023
#define II   32
#define EE   32
#define HH   256
#define KIN  64

#define NCTA 64
#define BPB  8
#define NTH  512     // 16 warps

// per-warp tile counts: warps 0,1: 60+48+48+16=172 ; warps 2-15: 156
#define TILES_W01 172
#define TILES_W   156
#define NTILE_TOT (2*TILES_W01 + 14*TILES_W)   // 2528
#define XSTR 328     // XB row stride in halfs ([x(64)|h0(256)] used)
#define HSTR 264     // H1B row stride in halfs

// fragment schedule: tile = 512B = 32 lanes x 8 halfs (a0..a3 order)
__device__ __align__(1024) __half SCHED[NTILE_TOT * 256];

// ---- prep: weights -> per-warp consumption-ordered HMMA A-fragments ----
__global__ void prep_kernel(const float* __restrict__ wih0, const float* __restrict__ whh0,
                            const float* __restrict__ wih1, const float* __restrict__ whh1,
                            const float* __restrict__ wout)
{
    int idx = blockIdx.x * blockDim.x + threadIdx.x;
    if (idx >= NTILE_TOT * 256) return;
    const int j    = idx & 7;
    const int lane = (idx >> 3) & 31;
    const int tile = idx >> 8;

    int w, r;
    if (tile < 2 * TILES_W01) { w = tile / TILES_W01; r = tile % TILES_W01; }
    else { w = 2 + (tile - 2 * TILES_W01) / TILES_W; r = (tile - 2 * TILES_W01) % TILES_W; }

    const int g  = lane >> 2;
    const int tq = lane & 3;
    const int il = g + 8 * ((j >> 1) & 1);            // row within tile
    const int kl = tq * 2 + (j & 1) + 8 * (j >> 2);   // k within tile

    float v;
    if (r < 60) {              // G0: per kt {r,z,in|hn}
        const int kt = r / 3, kind = r % 3;
        const int base = kind * 256;                  // kind2 -> rows 512 (in/hn)
        const int row = base + 16 * w + il;
        if (kt < 4) v = wih0[row * KIN + kt * 16 + kl];
        else        v = whh0[row * HH + (kt - 4) * 16 + kl];
    } else if (r < 108) {      // GB: Whh1 {r,z,hn}
        const int rr = r - 60, kt = rr / 3, kind = rr % 3;
        v = whh1[(kind * 256 + 16 * w + il) * HH + kt * 16 + kl];
    } else if (r < 156) {      // GC: Wih1 {r,z,in}
        const int rr = r - 108, kt = rr / 3, kind = rr % 3;
        v = wih1[(kind * 256 + 16 * w + il) * HH + kt * 16 + kl];
    } else {                   // GY: wout (warps 0,1 only)
        const int kt = r - 156;
        v = wout[(16 * w + il) * HH + kt * 16 + kl];
    }
    SCHED[tile * 256 + lane * 8 + j] = __float2half_rn(v);
}

// ---- math helpers ----
__device__ __forceinline__ float tanha(float x) {
    float y; asm("tanh.approx.f32 %0, %1;" : "=f"(y) : "f"(x)); return y;
}
__device__ __forceinline__ float siga(float x) {
    return fmaf(tanha(0.5f * x), 0.5f, 0.5f);
}
__device__ __forceinline__ void hmma(float* c, uint4 a, u32 b0, u32 b1) {
    asm volatile("mma.sync.aligned.m16n8k16.row.col.f32.f16.f16.f32 "
                 "{%0,%1,%2,%3}, {%4,%5,%6,%7}, {%8,%9}, {%0,%1,%2,%3};"
                 : "+f"(c[0]), "+f"(c[1]), "+f"(c[2]), "+f"(c[3])
                 : "r"(a.x), "r"(a.y), "r"(a.z), "r"(a.w), "r"(b0), "r"(b1));
}

__global__ void __launch_bounds__(NTH, 1)
arrnn_kernel(const float* __restrict__ X,
             const float* __restrict__ ENC,
             const int*   __restrict__ MASK,
             const float* __restrict__ bih0, const float* __restrict__ bhh0,
             const float* __restrict__ bih1, const float* __restrict__ bhh1,
             const float* __restrict__ bout,
             float* __restrict__ outseq, float* __restrict__ outh1,
             int write_h1)
{
    __shared__ __align__(16) __half XB[BPB][XSTR];   // [batch][x(0..63) | h0(64..319)]
    __shared__ __align__(16) __half H1B[BPB][HSTR];  // [batch][h1]
    __shared__ __align__(16) float  yf[BPB][II];

    const int tid  = threadIdx.x;
    const int wid  = tid >> 5;
    const int lane = tid & 31;
    const int g    = lane >> 2;
    const int tq   = lane & 3;
    const int b0g  = blockIdx.x * BPB;

    const int u1 = 16 * wid + g;
    const int u2 = u1 + 8;

    // biases (fixed per thread)
    const float br0a = bih0[u1] + bhh0[u1],             br0b = bih0[u2] + bhh0[u2];
    const float bz0a = bih0[u1 + 256] + bhh0[u1 + 256], bz0b = bih0[u2 + 256] + bhh0[u2 + 256];
    const float bi0a = bih0[u1 + 512],                  bi0b = bih0[u2 + 512];
    const float bn0a = bhh0[u1 + 512],                  bn0b = bhh0[u2 + 512];
    const float br1a = bih1[u1] + bhh1[u1],             br1b = bih1[u2] + bhh1[u2];
    const float bz1a = bih1[u1 + 256] + bhh1[u1 + 256], bz1b = bih1[u2 + 256] + bhh1[u2 + 256];
    const float bi1a = bih1[u1 + 512],                  bi1b = bih1[u2 + 512];
    const float bn1a = bhh1[u1 + 512],                  bn1b = bhh1[u2 + 512];
    const float bya  = (wid < 2) ? bout[16 * wid + g] : 0.0f;
    const float byb  = (wid < 2) ? bout[16 * wid + g + 8] : 0.0f;

    // h state masters: p0=(u1, 2tq) p1=(u1, 2tq+1) p2=(u2, 2tq) p3=(u2, 2tq+1)
    float h0[4] = {0.f, 0.f, 0.f, 0.f};
    float h1[4] = {0.f, 0.f, 0.f, 0.f};

    // zero activation buffers
    for (int i = tid; i < BPB * XSTR; i += NTH) (&XB[0][0])[i] = __float2half_rn(0.f);
    for (int i = tid; i < BPB * HSTR; i += NTH) (&H1B[0][0])[i] = __float2half_rn(0.f);
    for (int i = tid; i < BPB * II; i += NTH) (&yf[0][0])[i] = 0.f;
    __syncthreads();

    const __half* tpw = SCHED +
        (size_t)((wid < 2) ? wid * TILES_W01 : 2 * TILES_W01 + (wid - 2) * TILES_W) * 256
        + lane * 8;

    const int bb = tid >> 6;       // x-build batch
    const int kk = tid & 63;       // x-build k

    for (int t = 0; t < TM1; ++t) {
        // ---- Phase A: build x into XB[:, 0:64] ----
        {
            const int gb = b0g + bb;
            float v;
            if (kk < II) {
                const bool keep = (t == 0) || (MASK[gb * TT + t] != 0);
                v = keep ? X[((size_t)gb * TT + t) * II + kk] : yf[bb][kk];
            } else {
                v = ENC[((size_t)gb * TT + (t + 1)) * EE + (kk - II)];
            }
            XB[bb][kk] = __float2half_rn(v);
        }
        __syncthreads();   // bar1: XB complete (x new, h0 from prev epi0)

        const __half* tp = tpw;

        // ---- G0: layer0 gates over [x|h0old], k=320 ----
        float Cr[4] = {0.f,0.f,0.f,0.f}, Cz[4] = {0.f,0.f,0.f,0.f};
        float Ci[4] = {0.f,0.f,0.f,0.f}, Ch[4] = {0.f,0.f,0.f,0.f};
#pragma unroll
        for (int kt = 0; kt < 4; ++kt) {
            const u32 b0 = *(const u32*)&XB[g][kt * 16 + 2 * tq];
            const u32 b1 = *(const u32*)&XB[g][kt * 16 + 8 + 2 * tq];
            uint4 ar = *(const uint4*)tp; tp += 256;
            uint4 az = *(const uint4*)tp; tp += 256;
            uint4 ai = *(const uint4*)tp; tp += 256;
            hmma(Cr, ar, b0, b1); hmma(Cz, az, b0, b1); hmma(Ci, ai, b0, b1);
        }
#pragma unroll 4
        for (int kt = 4; kt < 20; ++kt) {
            const u32 b0 = *(const u32*)&XB[g][kt * 16 + 2 * tq];
            const u32 b1 = *(const u32*)&XB[g][kt * 16 + 8 + 2 * tq];
            uint4 ar = *(const uint4*)tp; tp += 256;
            uint4 az = *(const uint4*)tp; tp += 256;
            uint4 ah = *(const uint4*)tp; tp += 256;
            hmma(Cr, ar, b0, b1); hmma(Cz, az, b0, b1); hmma(Ch, ah, b0, b1);
        }

        // ---- GB: Whh1 x h1old ----
        float Dr[4] = {0.f,0.f,0.f,0.f}, Dz[4] = {0.f,0.f,0.f,0.f}, Dh[4] = {0.f,0.f,0.f,0.f};
#pragma unroll 4
        for (int kt = 0; kt < 16; ++kt) {
            const u32 b0 = *(const u32*)&H1B[g][kt * 16 + 2 * tq];
            const u32 b1 = *(const u32*)&H1B[g][kt * 16 + 8 + 2 * tq];
            uint4 ar = *(const uint4*)tp; tp += 256;
            uint4 az = *(const uint4*)tp; tp += 256;
            uint4 ah = *(const uint4*)tp; tp += 256;
            hmma(Dr, ar, b0, b1); hmma(Dz, az, b0, b1); hmma(Dh, ah, b0, b1);
        }
        __syncthreads();   // bar2: all XB/H1B reads for G0/GB done

        // ---- epi0 (in registers) -> h0new fp16 into XB[:,64:] ----
#pragma unroll
        for (int p = 0; p < 4; ++p) {
            const bool a = (p < 2);
            const float rr = siga(Cr[p] + (a ? br0a : br0b));
            const float zz = siga(Cz[p] + (a ? bz0a : bz0b));
            const float nn = tanha(Ci[p] + (a ? bi0a : bi0b) + rr * (Ch[p] + (a ? bn0a : bn0b)));
            h0[p] = (1.0f - zz) * nn + zz * h0[p];
            XB[2 * tq + (p & 1)][64 + (a ? u1 : u2)] = __float2half_rn(h0[p]);
        }
        __syncthreads();   // bar3: h0new visible

        // ---- GC: Wih1 x h0new (accumulate Dr,Dz; fresh Di) ----
        float Di[4] = {0.f,0.f,0.f,0.f};
#pragma unroll 4
        for (int kt = 0; kt < 16; ++kt) {
            const u32 b0 = *(const u32*)&XB[g][64 + kt * 16 + 2 * tq];
            const u32 b1 = *(const u32*)&XB[g][64 + kt * 16 + 8 + 2 * tq];
            uint4 ar = *(const uint4*)tp; tp += 256;
            uint4 az = *(const uint4*)tp; tp += 256;
            uint4 ai = *(const uint4*)tp; tp += 256;
            hmma(Dr, ar, b0, b1); hmma(Dz, az, b0, b1); hmma(Di, ai, b0, b1);
        }

        // ---- epi1 (warp-local, no barrier needed) -> h1new fp16 ----
#pragma unroll
        for (int p = 0; p < 4; ++p) {
            const bool a = (p < 2);
            const float rr = siga(Dr[p] + (a ? br1a : br1b));
            const float zz = siga(Dz[p] + (a ? bz1a : bz1b));
            const float nn = tanha(Di[p] + (a ? bi1a : bi1b) + rr * (Dh[p] + (a ? bn1a : bn1b)));
            h1[p] = (1.0f - zz) * nn + zz * h1[p];
            H1B[2 * tq + (p & 1)][a ? u1 : u2] = __float2half_rn(h1[p]);
        }
        __syncthreads();   // bar4: h1new visible

        // ---- GY: readout (warps 0,1) ----
        if (wid < 2) {
            float Y[4] = {0.f,0.f,0.f,0.f};
#pragma unroll 4
            for (int kt = 0; kt < 16; ++kt) {
                const u32 b0 = *(const u32*)&H1B[g][kt * 16 + 2 * tq];
                const u32 b1 = *(const u32*)&H1B[g][kt * 16 + 8 + 2 * tq];
                uint4 ay = *(const uint4*)tp; tp += 256;
                hmma(Y, ay, b0, b1);
            }
#pragma unroll
            for (int p = 0; p < 4; ++p) {
                const bool a = (p < 2);
                const int i = 16 * wid + g + (a ? 0 : 8);
                const int b = 2 * tq + (p & 1);
                const float y = Y[p] + (a ? bya : byb);
                yf[b][i] = y;
                outseq[((size_t)(b0g + b) * TM1 + t) * II + i] = y;
            }
        }
        __syncthreads();   // bar5: yf ready for next Phase A
    }

    if (write_h1) {
#pragma unroll
        for (int p = 0; p < 4; ++p) {
            const int b = b0g + 2 * tq + (p & 1);
            const int u = (p < 2) ? u1 : u2;
            outh1[(size_t)b * HH + u] = h1[p];
        }
    }
}

extern "C" void kernel_launch(void* const* d_in, const int* in_sizes, int n_in,
                              void* d_out, int out_size) {
    const float* X    = (const float*)d_in[0];
    const float* ENC  = (const float*)d_in[1];
    const int*   MASK = (const int*)d_in[2];
    const float* wih0 = (const float*)d_in[3];
    const float* whh0 = (const float*)d_in[4];
    const float* bih0 = (const float*)d_in[5];
    const float* bhh0 = (const float*)d_in[6];
    const float* wih1 = (const float*)d_in[7];
    const float* whh1 = (const float*)d_in[8];
    const float* bih1 = (const float*)d_in[9];
    const float* bhh1 = (const float*)d_in[10];
    const float* wout = (const float*)d_in[11];
    const float* bout = (const float*)d_in[12];

    float* outseq = (float*)d_out;
    const int seqsz = BB * TM1 * II;
    float* outh1  = outseq + seqsz;
    const int write_h1 = (out_size >= seqsz + BB * HH) ? 1 : 0;

    prep_kernel<<<(NTILE_TOT * 256 + 255) / 256, 256>>>(wih0, whh0, wih1, whh1, wout);

    arrnn_kernel<<<NCTA, NTH>>>(X, ENC, MASK,
                                bih0, bhh0, bih1, bhh1, bout,
                                outseq, outh1, write_h1);
}